// round 5
// baseline (speedup 1.0000x reference)
#include <cuda_runtime.h>
#include <math.h>

// VectorQuantizer: inputs [16,4096,64] f32, weight [1024,64] f32.
// Output layout (f32): [loss(1) | quantized(65536*64) | perplexity(1) | indices(65536)]
// out+1 only 4-byte aligned -> scalar (but coalesced) stores into out_q.

#define N_TOK   65536
#define DIM     64
#define NCODE   1024
#define TPB     256
#define TOKB    64                     // tokens per block
#define CCHUNK  64                     // codes staged per chunk
#define NCHUNK  (NCODE / CCHUNK)       // 16
#define KQ      (DIM / 4)              // 16 quads (16B) per row
#define NBLK    (N_TOK / TOKB)         // 1024

__device__ __align__(16) float g_wnorm[NCODE * DIM];
__device__ float g_wsq[NCODE];
__device__ int   g_counts[NCODE];
__device__ float g_partials[NBLK];
__device__ unsigned g_done;

#define FFMA2(acc, a, b) \
    asm("fma.rn.f32x2 %0, %1, %2, %0;" : "+l"(acc) : "l"(a), "l"(b))

__device__ __forceinline__ float f32x2_hsum(unsigned long long v) {
    float lo, hi;
    asm("mov.b64 {%0,%1}, %2;" : "=f"(lo), "=f"(hi) : "l"(v));
    return lo + hi;
}

// ---------------------------------------------------------------------------
// Kernel 1: prep — zero histogram/done, normalize codebook rows + wsq.
// ---------------------------------------------------------------------------
__global__ __launch_bounds__(128) void vq_prep(const float* __restrict__ w) {
    int r = blockIdx.x * 128 + threadIdx.x;
    if (r == 0) g_done = 0;
    if (r >= NCODE) return;
    g_counts[r] = 0;
    const float4* src = reinterpret_cast<const float4*>(w + (size_t)r * DIM);
    float v[DIM];
    float ss = 0.f;
#pragma unroll
    for (int i = 0; i < DIM / 4; i++) {
        float4 q = src[i];
        v[4*i+0] = q.x; v[4*i+1] = q.y; v[4*i+2] = q.z; v[4*i+3] = q.w;
        ss += q.x*q.x + q.y*q.y + q.z*q.z + q.w*q.w;
    }
    float inv = 1.0f / fmaxf(sqrtf(ss), 1e-12f);
    float sq = 0.f;
    float4* dst = reinterpret_cast<float4*>(g_wnorm + (size_t)r * DIM);
#pragma unroll
    for (int i = 0; i < DIM / 4; i++) {
        float4 q;
        q.x = v[4*i+0] * inv; q.y = v[4*i+1] * inv;
        q.z = v[4*i+2] * inv; q.w = v[4*i+3] * inv;
        sq += q.x*q.x + q.y*q.y + q.z*q.z + q.w*q.w;
        dst[i] = q;
    }
    g_wsq[r] = sq;
}

// ---------------------------------------------------------------------------
// Kernel 2: main — smem-tiled 4x4 outer product.
//   Thread (tx = tid&15, ty = tid>>4): 4 tokens (ty*4+i) x 4 codes (tx*4+j).
//   Both operands stream from transposed smem tiles [kq][entity] (conflict-free).
// ---------------------------------------------------------------------------
__global__ __launch_bounds__(TPB, 2) void vq_main(const float* __restrict__ x_in,
                                                  float* __restrict__ out_q,
                                                  float* __restrict__ out_idx,
                                                  float* __restrict__ out_loss,
                                                  float* __restrict__ out_perp) {
    __shared__ __align__(16) ulonglong2 sw[KQ * CCHUNK];  // 16 KB [kq][code]
    __shared__ __align__(16) ulonglong2 sx[KQ * TOKB];    // 16 KB [kq][tok]
    __shared__ float swsq[CCHUNK];
    __shared__ float sxsq[TOKB];
    __shared__ float mbd[16 * TOKB];                      // [tx][tok]
    __shared__ int   mbi[16 * TOKB];
    __shared__ int   sbi[TOKB];
    __shared__ float red[TPB];
    __shared__ bool  is_last;

    const int tid = threadIdx.x;
    const int tx  = tid & 15;
    const int ty  = tid >> 4;
    const int T0  = blockIdx.x * TOKB;

    // --- normalize 64 tokens into sx (transposed), one token per thread<64 ---
    if (tid < TOKB) {
        const float4* a4 = reinterpret_cast<const float4*>(x_in + (size_t)(T0 + tid) * DIM);
        float4 v[KQ];
        float ss = 0.f;
#pragma unroll
        for (int q = 0; q < KQ; q++) {
            v[q] = a4[q];
            ss = fmaf(v[q].x, v[q].x, ss); ss = fmaf(v[q].y, v[q].y, ss);
            ss = fmaf(v[q].z, v[q].z, ss); ss = fmaf(v[q].w, v[q].w, ss);
        }
        float inv = 1.0f / fmaxf(sqrtf(ss), 1e-12f);
        float sq = 0.f;
#pragma unroll
        for (int q = 0; q < KQ; q++) {
            float4 s;
            s.x = v[q].x * inv; s.y = v[q].y * inv;
            s.z = v[q].z * inv; s.w = v[q].w * inv;
            sq = fmaf(s.x, s.x, sq); sq = fmaf(s.y, s.y, sq);
            sq = fmaf(s.z, s.z, sq); sq = fmaf(s.w, s.w, sq);
            *reinterpret_cast<float4*>(&sx[q * TOKB + tid]) = s;
        }
        sxsq[tid] = sq;
    }

    float bd[4] = {INFINITY, INFINITY, INFINITY, INFINITY};
    int   bi[4] = {0, 0, 0, 0};

    for (int ch = 0; ch < NCHUNK; ch++) {
        const int c0 = ch * CCHUNK;
        __syncthreads();   // prev chunk readers done (also covers sx on ch==0)
        // stage w chunk transposed: sw[q][c] = g_wnorm[c0+c][quad q]
#pragma unroll
        for (int it = 0; it < (CCHUNK * KQ) / TPB; it++) {  // 4
            int f = it * TPB + tid;
            int c = f & (CCHUNK - 1);
            int q = f >> 6;
            *reinterpret_cast<float4*>(&sw[q * CCHUNK + c]) =
                reinterpret_cast<const float4*>(g_wnorm)[(size_t)(c0 + c) * KQ + q];
        }
        if (tid < CCHUNK) swsq[tid] = g_wsq[c0 + tid];
        __syncthreads();

        unsigned long long acc[4][4];
#pragma unroll
        for (int i = 0; i < 4; i++)
#pragma unroll
            for (int j = 0; j < 4; j++) acc[i][j] = 0ull;

#pragma unroll
        for (int q = 0; q < KQ; q++) {
            ulonglong2 xv0 = sx[q * TOKB + ty * 4 + 0];
            ulonglong2 xv1 = sx[q * TOKB + ty * 4 + 1];
            ulonglong2 xv2 = sx[q * TOKB + ty * 4 + 2];
            ulonglong2 xv3 = sx[q * TOKB + ty * 4 + 3];
            ulonglong2 wv0 = sw[q * CCHUNK + tx * 4 + 0];
            ulonglong2 wv1 = sw[q * CCHUNK + tx * 4 + 1];
            ulonglong2 wv2 = sw[q * CCHUNK + tx * 4 + 2];
            ulonglong2 wv3 = sw[q * CCHUNK + tx * 4 + 3];
            FFMA2(acc[0][0], xv0.x, wv0.x); FFMA2(acc[0][0], xv0.y, wv0.y);
            FFMA2(acc[0][1], xv0.x, wv1.x); FFMA2(acc[0][1], xv0.y, wv1.y);
            FFMA2(acc[0][2], xv0.x, wv2.x); FFMA2(acc[0][2], xv0.y, wv2.y);
            FFMA2(acc[0][3], xv0.x, wv3.x); FFMA2(acc[0][3], xv0.y, wv3.y);
            FFMA2(acc[1][0], xv1.x, wv0.x); FFMA2(acc[1][0], xv1.y, wv0.y);
            FFMA2(acc[1][1], xv1.x, wv1.x); FFMA2(acc[1][1], xv1.y, wv1.y);
            FFMA2(acc[1][2], xv1.x, wv2.x); FFMA2(acc[1][2], xv1.y, wv2.y);
            FFMA2(acc[1][3], xv1.x, wv3.x); FFMA2(acc[1][3], xv1.y, wv3.y);
            FFMA2(acc[2][0], xv2.x, wv0.x); FFMA2(acc[2][0], xv2.y, wv0.y);
            FFMA2(acc[2][1], xv2.x, wv1.x); FFMA2(acc[2][1], xv2.y, wv1.y);
            FFMA2(acc[2][2], xv2.x, wv2.x); FFMA2(acc[2][2], xv2.y, wv2.y);
            FFMA2(acc[2][3], xv2.x, wv3.x); FFMA2(acc[2][3], xv2.y, wv3.y);
            FFMA2(acc[3][0], xv3.x, wv0.x); FFMA2(acc[3][0], xv3.y, wv0.y);
            FFMA2(acc[3][1], xv3.x, wv1.x); FFMA2(acc[3][1], xv3.y, wv1.y);
            FFMA2(acc[3][2], xv3.x, wv2.x); FFMA2(acc[3][2], xv3.y, wv2.y);
            FFMA2(acc[3][3], xv3.x, wv3.x); FFMA2(acc[3][3], xv3.y, wv3.y);
        }

        // score + thread-local argmin (codes strictly ascending per thread ->
        // strict < reproduces jnp.argmin first-min within this thread's set)
#pragma unroll
        for (int j = 0; j < 4; j++) {
            float wq = swsq[tx * 4 + j];
            int code = c0 + tx * 4 + j;
#pragma unroll
            for (int i = 0; i < 4; i++) {
                float s = fmaf(-2.0f, f32x2_hsum(acc[i][j]), wq);
                if (s < bd[i]) { bd[i] = s; bi[i] = code; }
            }
        }
    }

    // --- publish per-thread candidates, merge across tx with (val, idx) lex ---
#pragma unroll
    for (int i = 0; i < 4; i++) {
        mbd[tx * TOKB + ty * 4 + i] = bd[i];
        mbi[tx * TOKB + ty * 4 + i] = bi[i];
    }
    __syncthreads();

    float myloss = 0.f;
    if (tid < TOKB) {
        float bv = mbd[tid];
        int   bx = mbi[tid];
#pragma unroll
        for (int g = 1; g < 16; g++) {
            float v = mbd[g * TOKB + tid];
            int   x = mbi[g * TOKB + tid];
            if (v < bv || (v == bv && x < bx)) { bv = v; bx = x; }
        }
        sbi[tid] = bx;
        out_idx[T0 + tid] = (float)bx;
        atomicAdd(&g_counts[bx], 1);
        myloss = sxsq[tid] + bv;     // ||q-x||^2 = xsq + (wsq - 2 dot)
    }
    __syncthreads();

    // --- coalesced quantized gather/store ---
#pragma unroll
    for (int it = 0; it < (TOKB * DIM) / TPB; it++) {    // 16
        int f = it * TPB + tid;
        int tok = f >> 6, lane = f & 63;
        out_q[(size_t)T0 * DIM + f] = g_wnorm[(size_t)sbi[tok] * DIM + lane];
    }

    // --- deterministic per-block loss partial ---
    red[tid] = myloss;
    __syncthreads();
#pragma unroll
    for (int s = TPB / 2; s > 0; s >>= 1) {
        if (tid < s) red[tid] += red[tid + s];
        __syncthreads();
    }
    if (tid == 0) {
        g_partials[blockIdx.x] = red[0];
        __threadfence();
        unsigned v = atomicAdd(&g_done, 1u);
        is_last = (v == NBLK - 1);
    }
    __syncthreads();

    // --- last block: finalize loss + perplexity (fixed order, deterministic) ---
    if (is_last) {
        __threadfence();
        float e = 0.f;
#pragma unroll
        for (int j = 0; j < NCODE / TPB; j++) {          // 4
            int c = __ldcg(&g_counts[tid * (NCODE / TPB) + j]);
            float p = (float)c * (1.0f / (float)N_TOK);
            e += p * logf(p + 1e-10f);
        }
        red[tid] = e;
        __syncthreads();
#pragma unroll
        for (int s = TPB / 2; s > 0; s >>= 1) {
            if (tid < s) red[tid] += red[tid + s];
            __syncthreads();
        }
        if (tid == 0) *out_perp = expf(-red[0]);
        __syncthreads();

        float l = 0.f;
#pragma unroll
        for (int j = 0; j < NBLK / TPB; j++)             // 4
            l += __ldcg(&g_partials[tid * (NBLK / TPB) + j]);
        red[tid] = l;
        __syncthreads();
#pragma unroll
        for (int s = TPB / 2; s > 0; s >>= 1) {
            if (tid < s) red[tid] += red[tid + s];
            __syncthreads();
        }
        if (tid == 0)
            *out_loss = 1.25f * (red[0] / (float)((long long)N_TOK * DIM));
    }
}

// ---------------------------------------------------------------------------
extern "C" void kernel_launch(void* const* d_in, const int* in_sizes, int n_in,
                              void* d_out, int out_size) {
    const float* x = (const float*)d_in[0];
    const float* w = (const float*)d_in[1];
    if (n_in >= 2 && in_sizes[0] < in_sizes[1]) {
        x = (const float*)d_in[1];
        w = (const float*)d_in[0];
    }

    float* out = (float*)d_out;
    const long long ND = (long long)N_TOK * DIM;
    float* out_loss = out;
    float* out_q    = out + 1;
    float* out_perp = out + 1 + ND;
    float* out_idx  = out + 2 + ND;

    vq_prep<<<8, 128>>>(w);
    vq_main<<<NBLK, TPB>>>(x, out_q, out_idx, out_loss, out_perp);
}

// round 6
// speedup vs baseline: 2.1168x; 2.1168x over previous
#include <cuda_runtime.h>
#include <math.h>

// VectorQuantizer: inputs [16,4096,64] f32, weight [1024,64] f32.
// Output layout (f32): [loss(1) | quantized(65536*64) | perplexity(1) | indices(65536)]
// out+1 only 4-byte aligned -> scalar (but coalesced) stores into out_q.

#define N_TOK   65536
#define DIM     64
#define NCODE   1024
#define TPB     256
#define TOKB    64                     // tokens per block
#define CCHUNK  64                     // codes staged per chunk
#define NCHUNK  (NCODE / CCHUNK)       // 16
#define KQ      (DIM / 4)              // 16 quads (16B) per row
#define NBLK    (N_TOK / TOKB)         // 1024

__device__ __align__(16) float g_wnorm[NCODE * DIM];
__device__ float g_wsq[NCODE];
__device__ int   g_counts[NCODE];
__device__ float g_partials[NBLK];
__device__ unsigned g_done;

#define FFMA2(acc, a, b) \
    asm("fma.rn.f32x2 %0, %1, %2, %0;" : "+l"(acc) : "l"(a), "l"(b))

__device__ __forceinline__ float f32x2_hsum(unsigned long long v) {
    float lo, hi;
    asm("mov.b64 {%0,%1}, %2;" : "=f"(lo), "=f"(hi) : "l"(v));
    return lo + hi;
}

// ---------------------------------------------------------------------------
// Kernel 1: prep — zero histogram/done, normalize codebook rows + wsq.
// ---------------------------------------------------------------------------
__global__ __launch_bounds__(128) void vq_prep(const float* __restrict__ w) {
    int r = blockIdx.x * 128 + threadIdx.x;
    if (r == 0) g_done = 0;
    if (r >= NCODE) return;
    g_counts[r] = 0;
    const float4* src = reinterpret_cast<const float4*>(w + (size_t)r * DIM);
    float v[DIM];
    float ss = 0.f;
#pragma unroll
    for (int i = 0; i < DIM / 4; i++) {
        float4 q = src[i];
        v[4*i+0] = q.x; v[4*i+1] = q.y; v[4*i+2] = q.z; v[4*i+3] = q.w;
        ss += q.x*q.x + q.y*q.y + q.z*q.z + q.w*q.w;
    }
    float inv = 1.0f / fmaxf(sqrtf(ss), 1e-12f);
    float sq = 0.f;
    float4* dst = reinterpret_cast<float4*>(g_wnorm + (size_t)r * DIM);
#pragma unroll
    for (int i = 0; i < DIM / 4; i++) {
        float4 q;
        q.x = v[4*i+0] * inv; q.y = v[4*i+1] * inv;
        q.z = v[4*i+2] * inv; q.w = v[4*i+3] * inv;
        sq += q.x*q.x + q.y*q.y + q.z*q.z + q.w*q.w;
        dst[i] = q;
    }
    g_wsq[r] = sq;
}

// ---------------------------------------------------------------------------
// Kernel 2: main — smem-tiled 4x4 outer product.
//   Thread (tx = tid&15, ty = tid>>4): 4 tokens (ty*4+i) x 4 codes
//   {tx, tx+16, tx+32, tx+48}  <-- lane-consecutive 16B addresses: the w-tile
//   LDS.128 is conflict-free (256 B contiguous per warp request).
//   x loads are warp-broadcast (<=2 addresses).
// ---------------------------------------------------------------------------
__global__ __launch_bounds__(TPB, 2) void vq_main(const float* __restrict__ x_in,
                                                  float* __restrict__ out_q,
                                                  float* __restrict__ out_idx,
                                                  float* __restrict__ out_loss,
                                                  float* __restrict__ out_perp) {
    __shared__ __align__(16) ulonglong2 sw[KQ * CCHUNK];  // 16 KB [kq][code]
    __shared__ __align__(16) ulonglong2 sx[KQ * TOKB];    // 16 KB [kq][tok]
    __shared__ float swsq[CCHUNK];
    __shared__ float sxsq[TOKB];
    __shared__ float mbd[16 * TOKB];                      // [tx][tok]
    __shared__ int   mbi[16 * TOKB];
    __shared__ int   sbi[TOKB];
    __shared__ float red[TPB];
    __shared__ bool  is_last;

    const int tid = threadIdx.x;
    const int tx  = tid & 15;
    const int ty  = tid >> 4;
    const int T0  = blockIdx.x * TOKB;

    // --- normalize 64 tokens into sx (transposed), one token per thread<64 ---
    if (tid < TOKB) {
        const float4* a4 = reinterpret_cast<const float4*>(x_in + (size_t)(T0 + tid) * DIM);
        float4 v[KQ];
        float ss = 0.f;
#pragma unroll
        for (int q = 0; q < KQ; q++) {
            v[q] = a4[q];
            ss = fmaf(v[q].x, v[q].x, ss); ss = fmaf(v[q].y, v[q].y, ss);
            ss = fmaf(v[q].z, v[q].z, ss); ss = fmaf(v[q].w, v[q].w, ss);
        }
        float inv = 1.0f / fmaxf(sqrtf(ss), 1e-12f);
        float sq = 0.f;
#pragma unroll
        for (int q = 0; q < KQ; q++) {
            float4 s;
            s.x = v[q].x * inv; s.y = v[q].y * inv;
            s.z = v[q].z * inv; s.w = v[q].w * inv;
            sq = fmaf(s.x, s.x, sq); sq = fmaf(s.y, s.y, sq);
            sq = fmaf(s.z, s.z, sq); sq = fmaf(s.w, s.w, sq);
            *reinterpret_cast<float4*>(&sx[q * TOKB + tid]) = s;
        }
        sxsq[tid] = sq;
    }

    float bd[4] = {INFINITY, INFINITY, INFINITY, INFINITY};
    int   bi[4] = {0, 0, 0, 0};

    for (int ch = 0; ch < NCHUNK; ch++) {
        const int c0 = ch * CCHUNK;
        __syncthreads();   // prev chunk readers done (also covers sx on ch==0)
        // stage w chunk transposed: sw[q][c] = g_wnorm[c0+c][quad q]
#pragma unroll
        for (int it = 0; it < (CCHUNK * KQ) / TPB; it++) {  // 4
            int f = it * TPB + tid;
            int c = f & (CCHUNK - 1);
            int q = f >> 6;
            *reinterpret_cast<float4*>(&sw[q * CCHUNK + c]) =
                reinterpret_cast<const float4*>(g_wnorm)[(size_t)(c0 + c) * KQ + q];
        }
        if (tid < CCHUNK) swsq[tid] = g_wsq[c0 + tid];
        __syncthreads();

        unsigned long long acc[4][4];    // [token i][code group j]
#pragma unroll
        for (int i = 0; i < 4; i++)
#pragma unroll
            for (int j = 0; j < 4; j++) acc[i][j] = 0ull;

#pragma unroll
        for (int q = 0; q < KQ; q++) {
            ulonglong2 xv0 = sx[q * TOKB + ty * 4 + 0];
            ulonglong2 xv1 = sx[q * TOKB + ty * 4 + 1];
            ulonglong2 xv2 = sx[q * TOKB + ty * 4 + 2];
            ulonglong2 xv3 = sx[q * TOKB + ty * 4 + 3];
            ulonglong2 wv0 = sw[q * CCHUNK + tx +  0];
            ulonglong2 wv1 = sw[q * CCHUNK + tx + 16];
            ulonglong2 wv2 = sw[q * CCHUNK + tx + 32];
            ulonglong2 wv3 = sw[q * CCHUNK + tx + 48];
            FFMA2(acc[0][0], xv0.x, wv0.x); FFMA2(acc[0][0], xv0.y, wv0.y);
            FFMA2(acc[0][1], xv0.x, wv1.x); FFMA2(acc[0][1], xv0.y, wv1.y);
            FFMA2(acc[0][2], xv0.x, wv2.x); FFMA2(acc[0][2], xv0.y, wv2.y);
            FFMA2(acc[0][3], xv0.x, wv3.x); FFMA2(acc[0][3], xv0.y, wv3.y);
            FFMA2(acc[1][0], xv1.x, wv0.x); FFMA2(acc[1][0], xv1.y, wv0.y);
            FFMA2(acc[1][1], xv1.x, wv1.x); FFMA2(acc[1][1], xv1.y, wv1.y);
            FFMA2(acc[1][2], xv1.x, wv2.x); FFMA2(acc[1][2], xv1.y, wv2.y);
            FFMA2(acc[1][3], xv1.x, wv3.x); FFMA2(acc[1][3], xv1.y, wv3.y);
            FFMA2(acc[2][0], xv2.x, wv0.x); FFMA2(acc[2][0], xv2.y, wv0.y);
            FFMA2(acc[2][1], xv2.x, wv1.x); FFMA2(acc[2][1], xv2.y, wv1.y);
            FFMA2(acc[2][2], xv2.x, wv2.x); FFMA2(acc[2][2], xv2.y, wv2.y);
            FFMA2(acc[2][3], xv2.x, wv3.x); FFMA2(acc[2][3], xv2.y, wv3.y);
            FFMA2(acc[3][0], xv3.x, wv0.x); FFMA2(acc[3][0], xv3.y, wv0.y);
            FFMA2(acc[3][1], xv3.x, wv1.x); FFMA2(acc[3][1], xv3.y, wv1.y);
            FFMA2(acc[3][2], xv3.x, wv2.x); FFMA2(acc[3][2], xv3.y, wv2.y);
            FFMA2(acc[3][3], xv3.x, wv3.x); FFMA2(acc[3][3], xv3.y, wv3.y);
        }

        // score + thread-local argmin; this thread's codes are c0 + j*16 + tx,
        // ascending in j -> strict < == first-min over the thread's subset.
#pragma unroll
        for (int j = 0; j < 4; j++) {
            float wq = swsq[j * 16 + tx];
            int code = c0 + j * 16 + tx;
#pragma unroll
            for (int i = 0; i < 4; i++) {
                float s = fmaf(-2.0f, f32x2_hsum(acc[i][j]), wq);
                if (s < bd[i]) { bd[i] = s; bi[i] = code; }
            }
        }
    }

    // --- publish per-thread candidates, merge across tx with (val, idx) lex ---
#pragma unroll
    for (int i = 0; i < 4; i++) {
        mbd[tx * TOKB + ty * 4 + i] = bd[i];
        mbi[tx * TOKB + ty * 4 + i] = bi[i];
    }
    __syncthreads();

    float myloss = 0.f;
    if (tid < TOKB) {
        float bv = mbd[tid];
        int   bx = mbi[tid];
#pragma unroll
        for (int g = 1; g < 16; g++) {
            float v = mbd[g * TOKB + tid];
            int   x = mbi[g * TOKB + tid];
            if (v < bv || (v == bv && x < bx)) { bv = v; bx = x; }
        }
        sbi[tid] = bx;
        out_idx[T0 + tid] = (float)bx;
        atomicAdd(&g_counts[bx], 1);
        myloss = sxsq[tid] + bv;     // ||q-x||^2 = xsq + (wsq - 2 dot)
    }
    __syncthreads();

    // --- coalesced quantized gather/store ---
#pragma unroll
    for (int it = 0; it < (TOKB * DIM) / TPB; it++) {    // 16
        int f = it * TPB + tid;
        int tok = f >> 6, lane = f & 63;
        out_q[(size_t)T0 * DIM + f] = g_wnorm[(size_t)sbi[tok] * DIM + lane];
    }

    // --- deterministic per-block loss partial ---
    red[tid] = myloss;
    __syncthreads();
#pragma unroll
    for (int s = TPB / 2; s > 0; s >>= 1) {
        if (tid < s) red[tid] += red[tid + s];
        __syncthreads();
    }
    if (tid == 0) {
        g_partials[blockIdx.x] = red[0];
        __threadfence();
        unsigned v = atomicAdd(&g_done, 1u);
        is_last = (v == NBLK - 1);
    }
    __syncthreads();

    // --- last block: finalize loss + perplexity (fixed order, deterministic) ---
    if (is_last) {
        __threadfence();
        float e = 0.f;
#pragma unroll
        for (int j = 0; j < NCODE / TPB; j++) {          // 4
            int c = __ldcg(&g_counts[tid * (NCODE / TPB) + j]);
            float p = (float)c * (1.0f / (float)N_TOK);
            e += p * logf(p + 1e-10f);
        }
        red[tid] = e;
        __syncthreads();
#pragma unroll
        for (int s = TPB / 2; s > 0; s >>= 1) {
            if (tid < s) red[tid] += red[tid + s];
            __syncthreads();
        }
        if (tid == 0) *out_perp = expf(-red[0]);
        __syncthreads();

        float l = 0.f;
#pragma unroll
        for (int j = 0; j < NBLK / TPB; j++)             // 4
            l += __ldcg(&g_partials[tid * (NBLK / TPB) + j]);
        red[tid] = l;
        __syncthreads();
#pragma unroll
        for (int s = TPB / 2; s > 0; s >>= 1) {
            if (tid < s) red[tid] += red[tid + s];
            __syncthreads();
        }
        if (tid == 0)
            *out_loss = 1.25f * (red[0] / (float)((long long)N_TOK * DIM));
    }
}

// ---------------------------------------------------------------------------
extern "C" void kernel_launch(void* const* d_in, const int* in_sizes, int n_in,
                              void* d_out, int out_size) {
    const float* x = (const float*)d_in[0];
    const float* w = (const float*)d_in[1];
    if (n_in >= 2 && in_sizes[0] < in_sizes[1]) {
        x = (const float*)d_in[1];
        w = (const float*)d_in[0];
    }

    float* out = (float*)d_out;
    const long long ND = (long long)N_TOK * DIM;
    float* out_loss = out;
    float* out_q    = out + 1;
    float* out_perp = out + 1 + ND;
    float* out_idx  = out + 2 + ND;

    vq_prep<<<8, 128>>>(w);
    vq_main<<<NBLK, TPB>>>(x, out_q, out_idx, out_loss, out_perp);
}

// round 7
// speedup vs baseline: 2.4350x; 1.1503x over previous
#include <cuda_runtime.h>
#include <math.h>

// VectorQuantizer: inputs [16,4096,64] f32, weight [1024,64] f32.
// Output layout (f32): [loss(1) | quantized(65536*64) | perplexity(1) | indices(65536)]
// out+1 only 4-byte aligned -> scalar stores into out_q.

#define N_TOK   65536
#define DIM     64
#define NCODE   1024
#define CHUNK   64                      // codes staged in smem per iteration
#define NCHUNK  (NCODE / CHUNK)         // 16
#define TPB     64                      // threads per block (2 warps)
#define TT      2                       // tokens per thread
#define TOK_PER_BLK (TPB * TT)          // 128
#define NBLK    (N_TOK / TOK_PER_BLK)   // 512

__device__ __align__(16) float g_wnorm[NCODE * DIM];
__device__ float g_wsq[NCODE];
__device__ int   g_counts[NCODE];
__device__ float g_partials[NBLK];
__device__ unsigned g_done;

#define FFMA2(acc, a, b) \
    asm("fma.rn.f32x2 %0, %1, %2, %0;" : "+l"(acc) : "l"(a), "l"(b))
#define MUL2(d, a, b) \
    asm("mul.rn.f32x2 %0, %1, %2;" : "=l"(d) : "l"(a), "l"(b))
#define PACK2(d, lo, hi) \
    asm("mov.b64 %0, {%1,%2};" : "=l"(d) : "f"(lo), "f"(hi))

__device__ __forceinline__ float f32x2_hsum(unsigned long long v) {
    float lo, hi;
    asm("mov.b64 {%0,%1}, %2;" : "=f"(lo), "=f"(hi) : "l"(v));
    return lo + hi;
}

// ---------------------------------------------------------------------------
// Kernel 1: prep — zero histogram/done, normalize codebook rows + wsq.
// ---------------------------------------------------------------------------
__global__ __launch_bounds__(128) void vq_prep(const float* __restrict__ w) {
    int r = blockIdx.x * 128 + threadIdx.x;
    if (r == 0) g_done = 0;
    if (r >= NCODE) return;
    g_counts[r] = 0;
    const float4* src = reinterpret_cast<const float4*>(w + (size_t)r * DIM);
    float v[DIM];
    float ss = 0.f;
#pragma unroll
    for (int i = 0; i < DIM / 4; i++) {
        float4 q = src[i];
        v[4*i+0] = q.x; v[4*i+1] = q.y; v[4*i+2] = q.z; v[4*i+3] = q.w;
        ss += q.x*q.x + q.y*q.y + q.z*q.z + q.w*q.w;
    }
    float inv = 1.0f / fmaxf(sqrtf(ss), 1e-12f);
    float sq = 0.f;
    float4* dst = reinterpret_cast<float4*>(g_wnorm + (size_t)r * DIM);
#pragma unroll
    for (int i = 0; i < DIM / 4; i++) {
        float4 q;
        q.x = v[4*i+0] * inv; q.y = v[4*i+1] * inv;
        q.z = v[4*i+2] * inv; q.w = v[4*i+3] * inv;
        sq += q.x*q.x + q.y*q.y + q.z*q.z + q.w*q.w;
        dst[i] = q;
    }
    g_wsq[r] = sq;
}

// ---------------------------------------------------------------------------
// 4-code x 2-token FFMA2 group: acc[c] = token0 dot code(kk+c),
//                               acc[4+c] = token1 dot code(kk+c).
// ---------------------------------------------------------------------------
__device__ __forceinline__ void mma_group(unsigned long long (&acc)[8],
                                          const float* __restrict__ sh, int kk,
                                          const unsigned long long (&xp0)[DIM/2],
                                          const unsigned long long (&xp1)[DIM/2]) {
#pragma unroll
    for (int i = 0; i < 8; i++) acc[i] = 0ull;
    const ulonglong2* wb = reinterpret_cast<const ulonglong2*>(sh + kk * DIM);
#pragma unroll
    for (int j = 0; j < DIM / 4; j++) {   // 16 iters: 4 LDS.128, 16 FFMA2
        ulonglong2 v0 = wb[j];
        ulonglong2 v1 = wb[16 + j];
        ulonglong2 v2 = wb[32 + j];
        ulonglong2 v3 = wb[48 + j];
        FFMA2(acc[0], xp0[2*j],   v0.x); FFMA2(acc[4], xp1[2*j],   v0.x);
        FFMA2(acc[1], xp0[2*j],   v1.x); FFMA2(acc[5], xp1[2*j],   v1.x);
        FFMA2(acc[2], xp0[2*j],   v2.x); FFMA2(acc[6], xp1[2*j],   v2.x);
        FFMA2(acc[3], xp0[2*j],   v3.x); FFMA2(acc[7], xp1[2*j],   v3.x);
        FFMA2(acc[0], xp0[2*j+1], v0.y); FFMA2(acc[4], xp1[2*j+1], v0.y);
        FFMA2(acc[1], xp0[2*j+1], v1.y); FFMA2(acc[5], xp1[2*j+1], v1.y);
        FFMA2(acc[2], xp0[2*j+1], v2.y); FFMA2(acc[6], xp1[2*j+1], v2.y);
        FFMA2(acc[3], xp0[2*j+1], v3.y); FFMA2(acc[7], xp1[2*j+1], v3.y);
    }
}

// Epilogue for one group: scores + argmin update (ascending code order,
// strict < == jnp.argmin first-min tiebreak).
__device__ __forceinline__ void epi_group(unsigned long long (&acc)[8],
                                          const float* __restrict__ shwsq,
                                          int c0, int kk,
                                          float& bd0, int& bi0,
                                          float& bd1, int& bi1) {
#pragma unroll
    for (int c = 0; c < 4; c++) {
        float wq = shwsq[kk + c];
        float s0 = fmaf(-2.0f, f32x2_hsum(acc[c]),     wq);
        float s1 = fmaf(-2.0f, f32x2_hsum(acc[4 + c]), wq);
        if (s0 < bd0) { bd0 = s0; bi0 = c0 + kk + c; }
        if (s1 < bd1) { bd1 = s1; bi1 = c0 + kk + c; }
    }
}

// ---------------------------------------------------------------------------
// Kernel 2: main — 2 tokens/thread in registers, w broadcast from smem,
// ping-pong accumulator sets so group g+1's FFMA2s overlap group g's epilogue.
// ---------------------------------------------------------------------------
__global__ __launch_bounds__(TPB) void vq_main(const float* __restrict__ x_in,
                                               float* __restrict__ out_q,
                                               float* __restrict__ out_idx,
                                               float* __restrict__ out_loss,
                                               float* __restrict__ out_perp) {
    __shared__ __align__(16) float sh[CHUNK * DIM];   // 16 KB
    __shared__ float shwsq[CHUNK];
    __shared__ float red[TPB];
    __shared__ bool  is_last;

    const int tid = threadIdx.x;
    const int t0  = blockIdx.x * TOK_PER_BLK + tid;
    const int t1  = t0 + TPB;

    // --- load + normalize both tokens, packed f32x2 only ---
    unsigned long long xp0[DIM / 2], xp1[DIM / 2];
    float xsq0, xsq1;
    {
        const float4* a4 = reinterpret_cast<const float4*>(x_in + (size_t)t0 * DIM);
        const float4* b4 = reinterpret_cast<const float4*>(x_in + (size_t)t1 * DIM);
        float ssa = 0.f, ssb = 0.f;
#pragma unroll
        for (int i = 0; i < DIM / 4; i++) {
            float4 q = a4[i];
            ssa = fmaf(q.x, q.x, ssa); ssa = fmaf(q.y, q.y, ssa);
            ssa = fmaf(q.z, q.z, ssa); ssa = fmaf(q.w, q.w, ssa);
            PACK2(xp0[2*i],   q.x, q.y);
            PACK2(xp0[2*i+1], q.z, q.w);
            float4 r = b4[i];
            ssb = fmaf(r.x, r.x, ssb); ssb = fmaf(r.y, r.y, ssb);
            ssb = fmaf(r.z, r.z, ssb); ssb = fmaf(r.w, r.w, ssb);
            PACK2(xp1[2*i],   r.x, r.y);
            PACK2(xp1[2*i+1], r.z, r.w);
        }
        float inva = 1.0f / fmaxf(sqrtf(ssa), 1e-12f);
        float invb = 1.0f / fmaxf(sqrtf(ssb), 1e-12f);
        unsigned long long ia, ib, sa = 0ull, sb = 0ull;
        PACK2(ia, inva, inva);
        PACK2(ib, invb, invb);
#pragma unroll
        for (int i = 0; i < DIM / 2; i++) {
            MUL2(xp0[i], xp0[i], ia);
            FFMA2(sa, xp0[i], xp0[i]);
            MUL2(xp1[i], xp1[i], ib);
            FFMA2(sb, xp1[i], xp1[i]);
        }
        xsq0 = f32x2_hsum(sa);
        xsq1 = f32x2_hsum(sb);
    }

    float bd0 = INFINITY, bd1 = INFINITY;
    int   bi0 = 0,        bi1 = 0;

    unsigned long long accA[8], accB[8];

    for (int ch = 0; ch < NCHUNK; ch++) {
        const int c0 = ch * CHUNK;
        __syncthreads();   // previous chunk's readers done before overwrite
        {
            const float4* src = reinterpret_cast<const float4*>(g_wnorm + (size_t)c0 * DIM);
            float4* dst = reinterpret_cast<float4*>(sh);
#pragma unroll
            for (int i = 0; i < (CHUNK * DIM / 4) / TPB; i++)   // 16
                dst[i * TPB + tid] = src[i * TPB + tid];
            shwsq[tid] = g_wsq[c0 + tid];   // TPB == CHUNK
        }
        __syncthreads();

        // 16 groups of 4 codes, ping-pong A/B so epilogues overlap FFMA2s.
        mma_group(accA, sh, 0, xp0, xp1);
#pragma unroll 1
        for (int gp = 0; gp < 7; gp++) {
            mma_group(accB, sh, (2*gp + 1) * 4, xp0, xp1);
            epi_group(accA, shwsq, c0, (2*gp + 0) * 4, bd0, bi0, bd1, bi1);
            mma_group(accA, sh, (2*gp + 2) * 4, xp0, xp1);
            epi_group(accB, shwsq, c0, (2*gp + 1) * 4, bd0, bi0, bd1, bi1);
        }
        mma_group(accB, sh, 15 * 4, xp0, xp1);
        epi_group(accA, shwsq, c0, 14 * 4, bd0, bi0, bd1, bi1);
        epi_group(accB, shwsq, c0, 15 * 4, bd0, bi0, bd1, bi1);
    }

    // --- outputs (scalar stores: out_q only 4B-aligned) ---
    {
        const float* wq0 = g_wnorm + (size_t)bi0 * DIM;
        float* qo0 = out_q + (size_t)t0 * DIM;
        const float* wq1 = g_wnorm + (size_t)bi1 * DIM;
        float* qo1 = out_q + (size_t)t1 * DIM;
#pragma unroll
        for (int i = 0; i < DIM; i++) { qo0[i] = wq0[i]; qo1[i] = wq1[i]; }
    }
    out_idx[t0] = (float)bi0;
    out_idx[t1] = (float)bi1;
    atomicAdd(&g_counts[bi0], 1);
    atomicAdd(&g_counts[bi1], 1);

    // --- per-block deterministic loss partial ---
    __syncthreads();
    red[tid] = (xsq0 + bd0) + (xsq1 + bd1);
    __syncthreads();
#pragma unroll
    for (int s = TPB / 2; s > 0; s >>= 1) {
        if (tid < s) red[tid] += red[tid + s];
        __syncthreads();
    }
    if (tid == 0) {
        g_partials[blockIdx.x] = red[0];
        __threadfence();
        unsigned v = atomicAdd(&g_done, 1u);
        is_last = (v == NBLK - 1);
    }
    __syncthreads();

    // --- last block: finalize loss + perplexity (fixed order, deterministic) ---
    if (is_last) {
        __threadfence();
        float e = 0.f;
#pragma unroll
        for (int j = 0; j < NCODE / TPB; j++) {          // 16
            int c = __ldcg(&g_counts[tid * (NCODE / TPB) + j]);
            float p = (float)c * (1.0f / (float)N_TOK);
            e += p * logf(p + 1e-10f);
        }
        red[tid] = e;
        __syncthreads();
#pragma unroll
        for (int s = TPB / 2; s > 0; s >>= 1) {
            if (tid < s) red[tid] += red[tid + s];
            __syncthreads();
        }
        if (tid == 0) *out_perp = expf(-red[0]);
        __syncthreads();

        float l = 0.f;
#pragma unroll
        for (int j = 0; j < NBLK / TPB; j++)             // 8
            l += __ldcg(&g_partials[tid * (NBLK / TPB) + j]);
        red[tid] = l;
        __syncthreads();
#pragma unroll
        for (int s = TPB / 2; s > 0; s >>= 1) {
            if (tid < s) red[tid] += red[tid + s];
            __syncthreads();
        }
        if (tid == 0)
            *out_loss = 1.25f * (red[0] / (float)((long long)N_TOK * DIM));
    }
}

// ---------------------------------------------------------------------------
extern "C" void kernel_launch(void* const* d_in, const int* in_sizes, int n_in,
                              void* d_out, int out_size) {
    const float* x = (const float*)d_in[0];
    const float* w = (const float*)d_in[1];
    if (n_in >= 2 && in_sizes[0] < in_sizes[1]) {
        x = (const float*)d_in[1];
        w = (const float*)d_in[0];
    }

    float* out = (float*)d_out;
    const long long ND = (long long)N_TOK * DIM;
    float* out_loss = out;
    float* out_q    = out + 1;
    float* out_perp = out + 1 + ND;
    float* out_idx  = out + 2 + ND;

    vq_prep<<<8, 128>>>(w);
    vq_main<<<NBLK, TPB>>>(x, out_q, out_idx, out_loss, out_perp);
}